// round 6
// baseline (speedup 1.0000x reference)
#include <cuda_runtime.h>
#include <cuda_bf16.h>
#include <math.h>

#define R 512
#define K 81
#define SCORE_THRESH 0.001f
#define MAX_PER_IMG 100
#define POST_NMS_TOPN 300
#define XFORM_CLIP 4.135166556742356f  /* log(1000/16) */
#define IM_W_M1 1332.0f
#define IM_H_M1 799.0f
#define TRI_TOTAL 4352                 /* sum_{w=0}^{15} 32*(w+1) */
#define TRI_Q 1088                     /* TRI_TOTAL / 4 */
#define NCLS 80                        /* classes 1..80 (class 0 always invalid) */

// Scratch (__device__ globals are zero-initialized at module load).
__device__ unsigned long long g_skey[K * R];        // sorted keys per class
__device__ float4             g_sbox[K * R];        // sorted boxes per class
__device__ float              g_sarea[K * R];       // sorted areas per class
__device__ unsigned           g_mask[K * R * 16];   // suppression bitmasks
__device__ unsigned long long g_rowkey[R];          // per-row argmax accum (self-zeroing)

// ---------------------------------------------------------------------------
// Box transform — single definition, identical rounding everywhere.
// ---------------------------------------------------------------------------
__device__ __forceinline__ float4 xform_box(const float* __restrict__ rois,
                                            const float* __restrict__ deltas,
                                            int r, int k) {
    float4 roi = reinterpret_cast<const float4*>(rois)[r];
    float4 dl  = *reinterpret_cast<const float4*>(deltas + r * (4 * K) + 4 * k);

    float w  = roi.z - roi.x + 1.0f;
    float h  = roi.w - roi.y + 1.0f;
    float cx = roi.x + 0.5f * w;
    float cy = roi.y + 0.5f * h;

    float dx = dl.x / 10.0f;
    float dy = dl.y / 10.0f;
    float dw = fminf(dl.z / 5.0f, XFORM_CLIP);
    float dh = fminf(dl.w / 5.0f, XFORM_CLIP);

    float pcx = dx * w + cx;
    float pcy = dy * h + cy;
    float pw  = expf(dw) * w;
    float ph  = expf(dh) * h;

    float ox1 = fminf(fmaxf(pcx - 0.5f * pw, 0.0f), IM_W_M1);
    float oy1 = fminf(fmaxf(pcy - 0.5f * ph, 0.0f), IM_H_M1);
    float ox2 = fminf(fmaxf(pcx + 0.5f * pw - 1.0f, 0.0f), IM_W_M1);
    float oy2 = fminf(fmaxf(pcy + 0.5f * ph - 1.0f, 0.0f), IM_H_M1);
    return make_float4(ox1, oy1, ox2, oy2);
}

// ---------------------------------------------------------------------------
// Hybrid bitonic sort of 512 unique uint64 keys, ascending.
// ---------------------------------------------------------------------------
__device__ __forceinline__ unsigned long long cswap_shfl(unsigned long long key,
                                                         int tid, int kk, int j) {
    unsigned long long pk = __shfl_xor_sync(0xffffffffu, key, j);
    bool asc   = ((tid & kk) == 0);
    bool lower = ((tid & j) == 0);
    bool cmp   = key > pk;
    bool take  = ((cmp == asc) == lower);
    return take ? pk : key;
}

__device__ __forceinline__ void sort512(unsigned long long* skey, int tid) {
    unsigned long long key = skey[tid];
#pragma unroll
    for (int kk = 2; kk <= 32; kk <<= 1)
#pragma unroll
        for (int j = kk >> 1; j > 0; j >>= 1)
            key = cswap_shfl(key, tid, kk, j);
    skey[tid] = key;
    __syncthreads();
#pragma unroll
    for (int kk = 64; kk <= 512; kk <<= 1) {
        for (int j = kk >> 1; j >= 32; j >>= 1) {
            int ixj = tid ^ j;
            if (ixj > tid) {
                bool up = ((tid & kk) == 0);
                unsigned long long a = skey[tid], b = skey[ixj];
                if ((a > b) == up) { skey[tid] = b; skey[ixj] = a; }
            }
            __syncthreads();
        }
        key = skey[tid];
#pragma unroll
        for (int j = 16; j > 0; j >>= 1)
            key = cswap_shfl(key, tid, kk, j);
        skey[tid] = key;
        __syncthreads();
    }
}

// ---------------------------------------------------------------------------
// Stage 1: per-class box transform + stable sort.  80 blocks x 512.
// ---------------------------------------------------------------------------
__global__ __launch_bounds__(R, 1) void sort_kernel(const float* __restrict__ rois,
                                                    const float* __restrict__ deltas,
                                                    const float* __restrict__ scores) {
    const int c   = blockIdx.x + 1;
    const int tid = threadIdx.x;

    __shared__ unsigned long long skey[R];   // 4 KB
    __shared__ float4 sboxO[R];              // 8 KB  (original order)
    __shared__ float  sareaO[R];             // 2 KB

    {
        float4 b = xform_box(rois, deltas, tid, c);
        sboxO[tid]  = b;
        sareaO[tid] = (b.z - b.x + 1.0f) * (b.w - b.y + 1.0f);
        unsigned sb = __float_as_uint(scores[tid * K + c]);
        skey[tid] = ((unsigned long long)(~sb) << 32) | (unsigned)tid;
    }
    __syncthreads();

    sort512(skey, tid);

    unsigned long long key = skey[tid];
    int oi = (unsigned)key;
    g_skey[c * R + tid]  = key;
    g_sbox[c * R + tid]  = sboxO[oi];
    g_sarea[c * R + tid] = sareaO[oi];
}

// ---------------------------------------------------------------------------
// Stage 2: suppression bitmask, balanced triangle split 4 ways per class.
// 320 blocks x 256 threads.
// ---------------------------------------------------------------------------
__global__ __launch_bounds__(256) void mask_kernel() {
    const int c   = (blockIdx.x >> 2) + 1;
    const int q   = blockIdx.x & 3;
    const int tid = threadIdx.x;

    __shared__ float4 sbox[R];    // 8 KB  (sorted order)
    __shared__ float  sarea[R];   // 2 KB

    for (int i = tid; i < R; i += 256) {
        sbox[i]  = g_sbox[c * R + i];
        sarea[i] = g_sarea[c * R + i];
    }
    __syncthreads();

    const int fend = (q + 1) * TRI_Q;
    for (int f = q * TRI_Q + tid; f < fend; f += 256) {
        int w = (int)((sqrtf(1.0f + (float)f * 0.25f) - 1.0f) * 0.5f);
        while (16 * (w + 1) * (w + 2) <= f) ++w;
        while (16 * w * (w + 1) > f) --w;
        int i = f - 16 * w * (w + 1);

        float4 bi = sbox[i];
        float  ai = sarea[i];
        unsigned bits = 0;
#pragma unroll
        for (int b = 0; b < 32; ++b) {
            int j = (w << 5) | b;
            float4 bj = sbox[j];              // broadcast across warp
            float  aj = sarea[j];
            float xx1 = fmaxf(bi.x, bj.x);
            float yy1 = fmaxf(bi.y, bj.y);
            float xx2 = fminf(bi.z, bj.z);
            float yy2 = fminf(bi.w, bj.w);
            float iw = fmaxf(xx2 - xx1 + 1.0f, 0.0f);
            float ih = fmaxf(yy2 - yy1 + 1.0f, 0.0f);
            float inter = iw * ih;
            float uni = ai + aj - inter;      // > 0 always (areas >= 1)
            if (inter + inter > uni) bits |= (1u << b);   // iou > 0.5
        }
        g_mask[c * (R * 16) + i * 16 + w] = bits;
    }
}

// ---------------------------------------------------------------------------
// Stage 3: greedy scan + per-row argmax accumulation.  80 blocks x 256.
// ---------------------------------------------------------------------------
__global__ __launch_bounds__(256, 1) void scan_kernel() {
    const int c   = blockIdx.x + 1;
    const int tid = threadIdx.x;

    __shared__ unsigned smask[R * 16];       // 32 KB
    __shared__ unsigned long long skey[R];   // 4 KB
    __shared__ unsigned skeepw[16];

    // Stage masks + keys into shared (vectorized, coalesced)
    {
        const uint4* src = reinterpret_cast<const uint4*>(g_mask + c * (R * 16));
        uint4* dst = reinterpret_cast<uint4*>(smask);
        for (int i = tid; i < R * 4; i += 256) dst[i] = src[i];
        for (int i = tid; i < R; i += 256) skey[i] = g_skey[c * R + i];
    }
    __syncthreads();

    // Greedy scan, chunked; lane w (<16) owns removal word w.
    if (tid < 32) {
        const int lane = tid;
        unsigned remv = 0, kw = 0;
        for (int ch = 0; ch < 16; ++ch) {
            unsigned kwc = 0;
            if (lane == ch) {
                unsigned diag[32];
#pragma unroll
                for (int j = 0; j < 32; ++j)
                    diag[j] = smask[(ch * 32 + j) * 16 + ch];
#pragma unroll
                for (int j = 0; j < 32; ++j) {
                    unsigned s = (unsigned)(((int)(remv << (31 - j))) >> 31);
                    kwc  |= (~s) & (1u << j);
                    remv |= diag[j] & ~s;
                }
                kw = kwc;
            }
            kwc = __shfl_sync(0xffffffffu, kwc, ch);
            if (lane > ch && lane < 16) {
#pragma unroll
                for (int j = 0; j < 32; ++j) {
                    unsigned live = (kwc >> j) & 1u;
                    remv |= smask[(ch * 32 + j) * 16 + lane] & (0u - live);
                }
            }
        }
        // POST_NMS_TOPN clamp
        int cnt = (lane < 16) ? __popc(kw) : 0;
        int incl = cnt;
        for (int off = 1; off < 16; off <<= 1) {
            int v = __shfl_up_sync(0xffffffffu, incl, off);
            if (lane >= off) incl += v;
        }
        int excl = incl - cnt;
        if (lane < 16) {
            if (excl >= POST_NMS_TOPN) {
                kw = 0;
            } else if (excl + cnt > POST_NMS_TOPN) {
                int allowed = POST_NMS_TOPN - excl;
                while (cnt > allowed) {
                    int hb = 31 - __clz(kw);
                    kw &= ~(1u << hb);
                    --cnt;
                }
            }
            skeepw[lane] = kw;
        }
    }
    __syncthreads();

    // Class validity (raw max score sits at sorted pos 0)
    float maxsc = __uint_as_float(~(unsigned)(skey[0] >> 32));
    bool cvalid = maxsc > SCORE_THRESH;      // c >= 1 by construction

    // Per-row argmax accumulation: key = score_bits<<32 | (K - c).
    // max => highest score; ties => smallest class (first-occurrence argmax).
    if (cvalid) {
        for (int p = tid; p < R; p += 256) {
            unsigned long long kk = skey[p];
            if ((skeepw[p >> 5] >> (p & 31)) & 1u) {
                unsigned sb = ~(unsigned)(kk >> 32);      // raw score bits (> 0)
                int orig = (unsigned)kk;
                unsigned long long v =
                    ((unsigned long long)sb << 32) | (unsigned)(K - c);
                atomicMax(&g_rowkey[orig], v);
            }
        }
    }
}

// ---------------------------------------------------------------------------
// Stage 4: decode per-row winners, stable top-100 sort, write outputs.
// Also re-zeroes g_rowkey so the next launch starts clean (graph replays).
// ---------------------------------------------------------------------------
__global__ __launch_bounds__(R, 1) void finalize_kernel(const float* __restrict__ rois,
                                                        const float* __restrict__ deltas,
                                                        float* __restrict__ out,
                                                        int out_size) {
    __shared__ unsigned long long skey[R];
    __shared__ int slabel[R];
    const int r = threadIdx.x;

    unsigned long long kv = g_rowkey[r];
    g_rowkey[r] = 0;                          // reset for next launch
    unsigned sb = (unsigned)(kv >> 32);       // score bits (0 if no winner)
    int label = kv ? (K - (int)(kv & 0xffffffffu)) : 0;

    skey[r] = ((unsigned long long)(~sb) << 32) | (unsigned)r;
    slabel[r] = label;
    __syncthreads();

    sort512(skey, r);

    if (r < MAX_PER_IMG) {
        unsigned long long kk = skey[r];
        int top = (unsigned)kk;
        float sc = __uint_as_float(~(unsigned)(kk >> 32));
        int lab = slabel[top];
        bool valid = sc > SCORE_THRESH;
        float4 b = xform_box(rois, deltas, top, lab);

        float osc = valid ? sc : 0.0f;
        float bx1 = valid ? b.x : 0.0f;
        float by1 = valid ? b.y : 0.0f;
        float bx2 = valid ? b.z : 0.0f;
        float by2 = valid ? b.w : 0.0f;

        int base = r * 5;
        if (base + 4 < out_size) {
            out[base + 0] = osc;
            out[base + 1] = bx1;
            out[base + 2] = by1;
            out[base + 3] = bx2;
            out[base + 4] = by2;
        }
        if (MAX_PER_IMG * 5 + r < out_size) out[MAX_PER_IMG * 5 + r] = (float)lab;
        if (MAX_PER_IMG * 6 + r < out_size) out[MAX_PER_IMG * 6 + r] = (float)top;
    }
}

// ---------------------------------------------------------------------------
extern "C" void kernel_launch(void* const* d_in, const int* in_sizes, int n_in,
                              void* d_out, int out_size) {
    const float* rois   = (const float*)d_in[0];
    const float* deltas = (const float*)d_in[1];
    const float* scores = (const float*)d_in[2];
    float* out = (float*)d_out;
    (void)in_sizes; (void)n_in;

    sort_kernel<<<NCLS, R>>>(rois, deltas, scores);
    mask_kernel<<<NCLS * 4, 256>>>();
    scan_kernel<<<NCLS, 256>>>();
    finalize_kernel<<<1, R>>>(rois, deltas, out, out_size);
}

// round 9
// speedup vs baseline: 1.0631x; 1.0631x over previous
#include <cuda_runtime.h>
#include <cuda_bf16.h>
#include <math.h>

#define R 512
#define K 81
#define SCORE_THRESH 0.001f
#define MAX_PER_IMG 100
#define POST_NMS_TOPN 300
#define XFORM_CLIP 4.135166556742356f  /* log(1000/16) */
#define IM_W_M1 1332.0f
#define IM_H_M1 799.0f
#define TRI_TOTAL 4352                 /* sum_{w=0}^{15} 32*(w+1) */
#define NCLS 80                        /* classes 1..80 (class 0 always invalid) */

// Scratch (__device__ globals zero-initialized at load; both are self-resetting
// every launch so graph replays start clean).
__device__ unsigned long long g_rowkey[R];   // per-row argmax accumulator
__device__ unsigned           g_done;        // completed-block counter

// ---------------------------------------------------------------------------
// Box transform — single definition, identical rounding everywhere.
// ---------------------------------------------------------------------------
__device__ __forceinline__ float4 xform_box(const float* __restrict__ rois,
                                            const float* __restrict__ deltas,
                                            int r, int k) {
    float4 roi = reinterpret_cast<const float4*>(rois)[r];
    float4 dl  = *reinterpret_cast<const float4*>(deltas + r * (4 * K) + 4 * k);

    float w  = roi.z - roi.x + 1.0f;
    float h  = roi.w - roi.y + 1.0f;
    float cx = roi.x + 0.5f * w;
    float cy = roi.y + 0.5f * h;

    float dx = dl.x / 10.0f;
    float dy = dl.y / 10.0f;
    float dw = fminf(dl.z / 5.0f, XFORM_CLIP);
    float dh = fminf(dl.w / 5.0f, XFORM_CLIP);

    float pcx = dx * w + cx;
    float pcy = dy * h + cy;
    float pw  = expf(dw) * w;
    float ph  = expf(dh) * h;

    float ox1 = fminf(fmaxf(pcx - 0.5f * pw, 0.0f), IM_W_M1);
    float oy1 = fminf(fmaxf(pcy - 0.5f * ph, 0.0f), IM_H_M1);
    float ox2 = fminf(fmaxf(pcx + 0.5f * pw - 1.0f, 0.0f), IM_W_M1);
    float oy2 = fminf(fmaxf(pcy + 0.5f * ph - 1.0f, 0.0f), IM_H_M1);
    return make_float4(ox1, oy1, ox2, oy2);
}

// ---------------------------------------------------------------------------
// Hybrid bitonic sort of 512 unique uint64 keys, ascending.
// ---------------------------------------------------------------------------
__device__ __forceinline__ unsigned long long cswap_shfl(unsigned long long key,
                                                         int tid, int kk, int j) {
    unsigned long long pk = __shfl_xor_sync(0xffffffffu, key, j);
    bool asc   = ((tid & kk) == 0);
    bool lower = ((tid & j) == 0);
    bool cmp   = key > pk;
    bool take  = ((cmp == asc) == lower);
    return take ? pk : key;
}

__device__ __forceinline__ void sort512(unsigned long long* skey, int tid) {
    unsigned long long key = skey[tid];
#pragma unroll
    for (int kk = 2; kk <= 32; kk <<= 1)
#pragma unroll
        for (int j = kk >> 1; j > 0; j >>= 1)
            key = cswap_shfl(key, tid, kk, j);
    skey[tid] = key;
    __syncthreads();
#pragma unroll
    for (int kk = 64; kk <= 512; kk <<= 1) {
        for (int j = kk >> 1; j >= 32; j >>= 1) {
            int ixj = tid ^ j;
            if (ixj > tid) {
                bool up = ((tid & kk) == 0);
                unsigned long long a = skey[tid], b = skey[ixj];
                if ((a > b) == up) { skey[tid] = b; skey[ixj] = a; }
            }
            __syncthreads();
        }
        key = skey[tid];
#pragma unroll
        for (int j = 16; j > 0; j >>= 1)
            key = cswap_shfl(key, tid, kk, j);
        skey[tid] = key;
        __syncthreads();
    }
}

// ---------------------------------------------------------------------------
// Single fused kernel: per-class {transform, sort, mask, scan, accumulate},
// then the LAST block to finish inlines the finalize (no extra launch).
// One block per class (1..80), 512 threads.
// ---------------------------------------------------------------------------
__global__ __launch_bounds__(R, 1) void detect_kernel(const float* __restrict__ rois,
                                                      const float* __restrict__ deltas,
                                                      const float* __restrict__ scores,
                                                      float* __restrict__ out,
                                                      int out_size) {
    const int c   = blockIdx.x + 1;
    const int tid = threadIdx.x;

    // 16B alignment REQUIRED: smask head is aliased as float4* below.
    __shared__ __align__(16) unsigned smask[R * 16];   // 32 KB
    __shared__ unsigned long long skey[R];             // 4 KB
    __shared__ float4 sboxS[R];                        // 8 KB  sorted-order boxes
    __shared__ float  sareaS[R];                       // 2 KB  sorted-order areas
    __shared__ unsigned skeepw[16];
    __shared__ int s_isLast;
    float4* sboxO = reinterpret_cast<float4*>(smask);            // 8 KB alias
    float*  sareaO = reinterpret_cast<float*>(smask + 2048 * 2); // +2 KB alias

    // Phase 1: box + stable sort key for this row
    {
        float4 b = xform_box(rois, deltas, tid, c);
        sboxO[tid]  = b;
        sareaO[tid] = (b.z - b.x + 1.0f) * (b.w - b.y + 1.0f);
        unsigned sb = __float_as_uint(scores[tid * K + c]);
        skey[tid] = ((unsigned long long)(~sb) << 32) | (unsigned)tid;
    }
    __syncthreads();

    // Phase 2: sort (ascending uint64 => score desc, idx asc)
    sort512(skey, tid);

    // Phase 3: gather boxes into sorted order, republish
    {
        int oi = (unsigned)skey[tid];
        float4 bi = sboxO[oi];
        float  ai = sareaO[oi];
        __syncthreads();                 // gathers done before alias reuse
        sboxS[tid]  = bi;
        sareaS[tid] = ai;
    }
    __syncthreads();

    // Phase 4: suppression bitmask, balanced triangle (columns w >= i>>5).
    for (int f = tid; f < TRI_TOTAL; f += R) {
        int w = (int)((sqrtf(1.0f + (float)f * 0.25f) - 1.0f) * 0.5f);
        while (16 * (w + 1) * (w + 2) <= f) ++w;
        while (16 * w * (w + 1) > f) --w;
        int i = f - 16 * w * (w + 1);

        float4 bi = sboxS[i];
        float  ai = sareaS[i];
        unsigned bits = 0;
#pragma unroll
        for (int b = 0; b < 32; ++b) {
            int j = (w << 5) | b;
            float4 bj = sboxS[j];            // broadcast across warp
            float  aj = sareaS[j];
            float xx1 = fmaxf(bi.x, bj.x);
            float yy1 = fmaxf(bi.y, bj.y);
            float xx2 = fminf(bi.z, bj.z);
            float yy2 = fminf(bi.w, bj.w);
            float iw = fmaxf(xx2 - xx1 + 1.0f, 0.0f);
            float ih = fmaxf(yy2 - yy1 + 1.0f, 0.0f);
            float inter = iw * ih;
            float uni = ai + aj - inter;     // > 0 always (areas >= 1)
            if (inter + inter > uni) bits |= (1u << b);   // iou > 0.5
        }
        smask[i * 16 + w] = bits;
    }
    __syncthreads();

    // Phase 5: greedy scan, chunked. Lane w (<16) owns removal word w.
    if (tid < 32) {
        const int lane = tid;
        unsigned remv = 0, kw = 0;
        for (int ch = 0; ch < 16; ++ch) {
            unsigned kwc = 0;
            if (lane == ch) {
                unsigned diag[32];
#pragma unroll
                for (int j = 0; j < 32; ++j)
                    diag[j] = smask[(ch * 32 + j) * 16 + ch];
#pragma unroll
                for (int j = 0; j < 32; ++j) {
                    unsigned s = (unsigned)(((int)(remv << (31 - j))) >> 31);
                    kwc  |= (~s) & (1u << j);
                    remv |= diag[j] & ~s;
                }
                kw = kwc;
            }
            kwc = __shfl_sync(0xffffffffu, kwc, ch);
            if (lane > ch && lane < 16) {
#pragma unroll
                for (int j = 0; j < 32; ++j) {
                    unsigned live = (kwc >> j) & 1u;
                    remv |= smask[(ch * 32 + j) * 16 + lane] & (0u - live);
                }
            }
        }
        // POST_NMS_TOPN clamp: keep first 300 kept (sorted order)
        int cnt = (lane < 16) ? __popc(kw) : 0;
        int incl = cnt;
        for (int off = 1; off < 16; off <<= 1) {
            int v = __shfl_up_sync(0xffffffffu, incl, off);
            if (lane >= off) incl += v;
        }
        int excl = incl - cnt;
        if (lane < 16) {
            if (excl >= POST_NMS_TOPN) {
                kw = 0;
            } else if (excl + cnt > POST_NMS_TOPN) {
                int allowed = POST_NMS_TOPN - excl;
                while (cnt > allowed) {
                    int hb = 31 - __clz(kw);
                    kw &= ~(1u << hb);
                    --cnt;
                }
            }
            skeepw[lane] = kw;
        }
    }
    __syncthreads();

    // Phase 6: class validity + per-row argmax accumulation.
    // key = score_bits<<32 | (K - c): max => highest score, ties => smallest
    // class = first-occurrence argmax. Bit-exact score carried through.
    {
        float maxsc = __uint_as_float(~(unsigned)(skey[0] >> 32));
        bool cvalid = maxsc > SCORE_THRESH;          // c >= 1 by construction
        unsigned long long kk = skey[tid];
        bool kept = (skeepw[tid >> 5] >> (tid & 31)) & 1u;
        if (cvalid && kept) {
            unsigned sb = ~(unsigned)(kk >> 32);     // raw score bits (> 0)
            int orig = (unsigned)kk;
            atomicMax(&g_rowkey[orig],
                      ((unsigned long long)sb << 32) | (unsigned)(K - c));
        }
    }

    // Phase 7: completion handshake; last block inlines the finalize.
    __threadfence();                 // make this block's atomics globally visible
    __syncthreads();
    if (tid == 0) {
        unsigned ticket = atomicAdd(&g_done, 1u);
        s_isLast = (ticket == NCLS - 1);
        if (s_isLast) g_done = 0;    // reset for next launch (sole accessor now)
    }
    __syncthreads();
    if (!s_isLast) return;

    // ---- Inline finalize (runs once, on the last-finishing block) ----
    int* flabel = reinterpret_cast<int*>(smask);     // alias, masks done

    {
        // atomicExch = coherent L2 read + self-resetting scratch
        unsigned long long kv = atomicExch(&g_rowkey[tid], 0ULL);
        unsigned sb = (unsigned)(kv >> 32);          // 0 if no winner
        flabel[tid] = kv ? (K - (int)(kv & 0xffffffffu)) : 0;
        skey[tid] = ((unsigned long long)(~sb) << 32) | (unsigned)tid;
    }
    __syncthreads();

    sort512(skey, tid);

    if (tid < MAX_PER_IMG) {
        unsigned long long kk = skey[tid];
        int top = (unsigned)kk;
        float sc = __uint_as_float(~(unsigned)(kk >> 32));
        int lab = flabel[top];
        bool valid = sc > SCORE_THRESH;
        float4 b = xform_box(rois, deltas, top, lab);

        float osc = valid ? sc : 0.0f;
        float bx1 = valid ? b.x : 0.0f;
        float by1 = valid ? b.y : 0.0f;
        float bx2 = valid ? b.z : 0.0f;
        float by2 = valid ? b.w : 0.0f;

        int base = tid * 5;
        if (base + 4 < out_size) {
            out[base + 0] = osc;
            out[base + 1] = bx1;
            out[base + 2] = by1;
            out[base + 3] = bx2;
            out[base + 4] = by2;
        }
        if (MAX_PER_IMG * 5 + tid < out_size) out[MAX_PER_IMG * 5 + tid] = (float)lab;
        if (MAX_PER_IMG * 6 + tid < out_size) out[MAX_PER_IMG * 6 + tid] = (float)top;
    }
}

// ---------------------------------------------------------------------------
extern "C" void kernel_launch(void* const* d_in, const int* in_sizes, int n_in,
                              void* d_out, int out_size) {
    const float* rois   = (const float*)d_in[0];
    const float* deltas = (const float*)d_in[1];
    const float* scores = (const float*)d_in[2];
    float* out = (float*)d_out;
    (void)in_sizes; (void)n_in;

    detect_kernel<<<NCLS, R>>>(rois, deltas, scores, out, out_size);
}

// round 12
// speedup vs baseline: 1.0807x; 1.0165x over previous
#include <cuda_runtime.h>
#include <cuda_bf16.h>
#include <math.h>

#define R 512
#define K 81
#define SCORE_THRESH 0.001f
#define MAX_PER_IMG 100
#define POST_NMS_TOPN 300
#define XFORM_CLIP 4.135166556742356f  /* log(1000/16) */
#define IM_W_M1 1332.0f
#define IM_H_M1 799.0f
#define TRI_TOTAL 4352                 /* sum_{w=0}^{15} 32*(w+1) */
#define NCLS 80                        /* classes 1..80 (class 0 always invalid) */
#define GRID 148                       /* <= SM count: all blocks co-resident */
#define ITEMS (NCLS * TRI_TOTAL)       /* 348160 mask-words total */
#define CHUNK ((ITEMS + GRID - 1) / GRID)  /* 2353 */

// ---- global scratch (zero-init at load) ----
__device__ unsigned           g_bar1, g_bar2;   // grid-sync tickets, MONOTONIC (never reset)
__device__ unsigned           g_done;           // scan ticket (reset by finalize, R9 pattern)
__device__ unsigned long long g_rowkey[R];      // per-row argmax accum (self-resetting)
__device__ unsigned long long g_skeyG[NCLS * R];
__device__ float4             g_sboxG[NCLS * R];
__device__ float              g_sareaG[NCLS * R];
__device__ unsigned           g_maskG[NCLS * R * 16];

// ---------------------------------------------------------------------------
__device__ __forceinline__ float4 xform_box(const float* __restrict__ rois,
                                            const float* __restrict__ deltas,
                                            int r, int k) {
    float4 roi = reinterpret_cast<const float4*>(rois)[r];
    float4 dl  = *reinterpret_cast<const float4*>(deltas + r * (4 * K) + 4 * k);

    float w  = roi.z - roi.x + 1.0f;
    float h  = roi.w - roi.y + 1.0f;
    float cx = roi.x + 0.5f * w;
    float cy = roi.y + 0.5f * h;

    float dx = dl.x / 10.0f;
    float dy = dl.y / 10.0f;
    float dw = fminf(dl.z / 5.0f, XFORM_CLIP);
    float dh = fminf(dl.w / 5.0f, XFORM_CLIP);

    float pcx = dx * w + cx;
    float pcy = dy * h + cy;
    float pw  = expf(dw) * w;
    float ph  = expf(dh) * h;

    float ox1 = fminf(fmaxf(pcx - 0.5f * pw, 0.0f), IM_W_M1);
    float oy1 = fminf(fmaxf(pcy - 0.5f * ph, 0.0f), IM_H_M1);
    float ox2 = fminf(fmaxf(pcx + 0.5f * pw - 1.0f, 0.0f), IM_W_M1);
    float oy2 = fminf(fmaxf(pcy + 0.5f * ph - 1.0f, 0.0f), IM_H_M1);
    return make_float4(ox1, oy1, ox2, oy2);
}

// ---------------------------------------------------------------------------
__device__ __forceinline__ unsigned long long cswap_shfl(unsigned long long key,
                                                         int tid, int kk, int j) {
    unsigned long long pk = __shfl_xor_sync(0xffffffffu, key, j);
    bool asc   = ((tid & kk) == 0);
    bool lower = ((tid & j) == 0);
    bool cmp   = key > pk;
    bool take  = ((cmp == asc) == lower);
    return take ? pk : key;
}

__device__ __forceinline__ void sort512(unsigned long long* skey, int tid) {
    unsigned long long key = skey[tid];
#pragma unroll
    for (int kk = 2; kk <= 32; kk <<= 1)
#pragma unroll
        for (int j = kk >> 1; j > 0; j >>= 1)
            key = cswap_shfl(key, tid, kk, j);
    skey[tid] = key;
    __syncthreads();
#pragma unroll
    for (int kk = 64; kk <= 512; kk <<= 1) {
        for (int j = kk >> 1; j >= 32; j >>= 1) {
            int ixj = tid ^ j;
            if (ixj > tid) {
                bool up = ((tid & kk) == 0);
                unsigned long long a = skey[tid], b = skey[ixj];
                if ((a > b) == up) { skey[tid] = b; skey[ixj] = a; }
            }
            __syncthreads();
        }
        key = skey[tid];
#pragma unroll
        for (int j = 16; j > 0; j >>= 1)
            key = cswap_shfl(key, tid, kk, j);
        skey[tid] = key;
        __syncthreads();
    }
}

// ---------------------------------------------------------------------------
// Grid-wide sync. Safe: grid==148 <= SM count -> all blocks co-resident.
// Monotonic counter (never reset) => correct across CUDA-graph replays.
// ---------------------------------------------------------------------------
__device__ __forceinline__ void grid_sync(unsigned* bar) {
    __syncthreads();
    if (threadIdx.x == 0) {
        __threadfence();
        unsigned t = atomicAdd(bar, 1u);
        unsigned target = t - (t % GRID) + GRID;
        while ((int)(*(volatile unsigned*)bar - target) < 0) __nanosleep(64);
    }
    __syncthreads();
}

// ---------------------------------------------------------------------------
// One kernel, 148 blocks x 512:
//   A (blk<80): transform+sort class -> global     | others wait
//   B (all):    flat-partitioned suppression masks over the whole chip
//   C (blk<80): scan + argmax accumulate; last scan block inlines finalize
// ---------------------------------------------------------------------------
__global__ __launch_bounds__(R, 1) void detect_kernel(const float* __restrict__ rois,
                                                      const float* __restrict__ deltas,
                                                      const float* __restrict__ scores,
                                                      float* __restrict__ out,
                                                      int out_size) {
    const int bid = blockIdx.x;
    const int tid = threadIdx.x;

    // 16B alignment REQUIRED: smask head aliased as float4*.
    __shared__ __align__(16) unsigned smask[R * 16];   // 32 KB
    __shared__ unsigned long long skey[R];             // 4 KB
    __shared__ float4 sboxS[R];                        // 8 KB
    __shared__ float  sareaS[R];                       // 2 KB
    __shared__ unsigned skeepw[16];
    __shared__ int s_isLast;
    float4* sboxO  = reinterpret_cast<float4*>(smask);            // 8 KB alias
    float*  sareaO = reinterpret_cast<float*>(smask + 2048 * 2);  // alias @16KB

    // ---------------- Phase A: per-class transform + sort ----------------
    if (bid < NCLS) {
        const int c = bid + 1;
        float4 b = xform_box(rois, deltas, tid, c);
        sboxO[tid]  = b;
        sareaO[tid] = (b.z - b.x + 1.0f) * (b.w - b.y + 1.0f);
        unsigned sb = __float_as_uint(scores[tid * K + c]);
        skey[tid] = ((unsigned long long)(~sb) << 32) | (unsigned)tid;
        __syncthreads();

        sort512(skey, tid);

        unsigned long long kk = skey[tid];
        int oi = (unsigned)kk;
        g_skeyG[bid * R + tid]  = kk;
        g_sboxG[bid * R + tid]  = sboxO[oi];
        g_sareaG[bid * R + tid] = sareaO[oi];
    }
    grid_sync(&g_bar1);

    // ---------------- Phase B: masks, flat-partitioned chip-wide ----------
    {
        int fstart = bid * CHUNK;
        int fend   = min(fstart + CHUNK, ITEMS);
        int c0 = fstart / TRI_TOTAL;
        int c1 = (fend - 1) / TRI_TOTAL;
        for (int cls = c0; cls <= c1; ++cls) {
            __syncthreads();                         // protect staging buffers
            sboxS[tid]  = g_sboxG[cls * R + tid];
            sareaS[tid] = g_sareaG[cls * R + tid];
            __syncthreads();

            int s0 = max(fstart, cls * TRI_TOTAL);
            int s1 = min(fend, (cls + 1) * TRI_TOTAL);
            for (int f = s0 + tid; f < s1; f += R) {
                int fl = f - cls * TRI_TOTAL;
                int w = (int)((sqrtf(1.0f + (float)fl * 0.25f) - 1.0f) * 0.5f);
                while (16 * (w + 1) * (w + 2) <= fl) ++w;
                while (16 * w * (w + 1) > fl) --w;
                int i = fl - 16 * w * (w + 1);

                float4 bi = sboxS[i];
                float  ai = sareaS[i];
                unsigned bits = 0;
#pragma unroll
                for (int b = 0; b < 32; ++b) {
                    int j = (w << 5) | b;
                    float4 bj = sboxS[j];            // broadcast across warp
                    float  aj = sareaS[j];
                    float xx1 = fmaxf(bi.x, bj.x);
                    float yy1 = fmaxf(bi.y, bj.y);
                    float xx2 = fminf(bi.z, bj.z);
                    float yy2 = fminf(bi.w, bj.w);
                    float iw = fmaxf(xx2 - xx1 + 1.0f, 0.0f);
                    float ih = fmaxf(yy2 - yy1 + 1.0f, 0.0f);
                    float inter = iw * ih;
                    float uni = ai + aj - inter;     // > 0 always
                    if (inter + inter > uni) bits |= (1u << b);   // iou > 0.5
                }
                g_maskG[cls * (R * 16) + i * 16 + w] = bits;
            }
        }
    }
    grid_sync(&g_bar2);
    if (bid >= NCLS) return;

    // ---------------- Phase C: stage mask + scan + accumulate -------------
    {
        const uint4* src = reinterpret_cast<const uint4*>(g_maskG + bid * (R * 16));
        uint4* dst = reinterpret_cast<uint4*>(smask);
        for (int i = tid; i < R * 4; i += R) dst[i] = src[i];
        skey[tid] = g_skeyG[bid * R + tid];
    }
    __syncthreads();

    if (tid < 32) {
        const int lane = tid;
        unsigned remv = 0, kw = 0;
        for (int ch = 0; ch < 16; ++ch) {
            unsigned kwc = 0;
            if (lane == ch) {
                unsigned diag[32];
#pragma unroll
                for (int j = 0; j < 32; ++j)
                    diag[j] = smask[(ch * 32 + j) * 16 + ch];
#pragma unroll
                for (int j = 0; j < 32; ++j) {
                    unsigned s = (unsigned)(((int)(remv << (31 - j))) >> 31);
                    kwc  |= (~s) & (1u << j);
                    remv |= diag[j] & ~s;
                }
                kw = kwc;
            }
            kwc = __shfl_sync(0xffffffffu, kwc, ch);
            if (lane > ch && lane < 16) {
#pragma unroll
                for (int j = 0; j < 32; ++j) {
                    unsigned live = (kwc >> j) & 1u;
                    remv |= smask[(ch * 32 + j) * 16 + lane] & (0u - live);
                }
            }
        }
        // POST_NMS_TOPN clamp: keep first 300 kept (sorted order)
        int cnt = (lane < 16) ? __popc(kw) : 0;
        int incl = cnt;
        for (int off = 1; off < 16; off <<= 1) {
            int v = __shfl_up_sync(0xffffffffu, incl, off);
            if (lane >= off) incl += v;
        }
        int excl = incl - cnt;
        if (lane < 16) {
            if (excl >= POST_NMS_TOPN) {
                kw = 0;
            } else if (excl + cnt > POST_NMS_TOPN) {
                int allowed = POST_NMS_TOPN - excl;
                while (cnt > allowed) {
                    int hb = 31 - __clz(kw);
                    kw &= ~(1u << hb);
                    --cnt;
                }
            }
            skeepw[lane] = kw;
        }
    }
    __syncthreads();

    // validity + per-row argmax accumulation (exact, first-occurrence ties)
    {
        const int c = bid + 1;
        float maxsc = __uint_as_float(~(unsigned)(skey[0] >> 32));
        bool cvalid = maxsc > SCORE_THRESH;
        unsigned long long kk = skey[tid];
        bool kept = (skeepw[tid >> 5] >> (tid & 31)) & 1u;
        if (cvalid && kept) {
            unsigned sb = ~(unsigned)(kk >> 32);
            int orig = (unsigned)kk;
            atomicMax(&g_rowkey[orig],
                      ((unsigned long long)sb << 32) | (unsigned)(K - c));
        }
    }

    // completion ticket; last scan block inlines the finalize
    __threadfence();
    __syncthreads();
    if (tid == 0) {
        unsigned ticket = atomicAdd(&g_done, 1u);
        s_isLast = (ticket == NCLS - 1);
        if (s_isLast) g_done = 0;     // sole accessor now; reset for next launch
    }
    __syncthreads();
    if (!s_isLast) return;

    // ---- Inline finalize ----
    int* flabel = reinterpret_cast<int*>(smask);
    {
        unsigned long long kv = atomicExch(&g_rowkey[tid], 0ULL);
        unsigned sb = (unsigned)(kv >> 32);
        flabel[tid] = kv ? (K - (int)(kv & 0xffffffffu)) : 0;
        skey[tid] = ((unsigned long long)(~sb) << 32) | (unsigned)tid;
    }
    __syncthreads();

    sort512(skey, tid);

    if (tid < MAX_PER_IMG) {
        unsigned long long kk = skey[tid];
        int top = (unsigned)kk;
        float sc = __uint_as_float(~(unsigned)(kk >> 32));
        int lab = flabel[top];
        bool valid = sc > SCORE_THRESH;
        float4 b = xform_box(rois, deltas, top, lab);

        float osc = valid ? sc : 0.0f;
        float bx1 = valid ? b.x : 0.0f;
        float by1 = valid ? b.y : 0.0f;
        float bx2 = valid ? b.z : 0.0f;
        float by2 = valid ? b.w : 0.0f;

        int base = tid * 5;
        if (base + 4 < out_size) {
            out[base + 0] = osc;
            out[base + 1] = bx1;
            out[base + 2] = by1;
            out[base + 3] = bx2;
            out[base + 4] = by2;
        }
        if (MAX_PER_IMG * 5 + tid < out_size) out[MAX_PER_IMG * 5 + tid] = (float)lab;
        if (MAX_PER_IMG * 6 + tid < out_size) out[MAX_PER_IMG * 6 + tid] = (float)top;
    }
}

// ---------------------------------------------------------------------------
extern "C" void kernel_launch(void* const* d_in, const int* in_sizes, int n_in,
                              void* d_out, int out_size) {
    const float* rois   = (const float*)d_in[0];
    const float* deltas = (const float*)d_in[1];
    const float* scores = (const float*)d_in[2];
    float* out = (float*)d_out;
    (void)in_sizes; (void)n_in;

    detect_kernel<<<GRID, R>>>(rois, deltas, scores, out, out_size);
}